// round 3
// baseline (speedup 1.0000x reference)
#include <cuda_runtime.h>

// Problem constants
#define HH   56
#define WW2  56
#define HWP  3136      // 56*56
#define LL   25088     // 8*3136 pixels
#define CCH  256       // channels
#define DDIM 2304      // 256*9
#define BK   16
#define ROWW 132       // padded smem row (breaks transpose-store bank conflicts, keeps 16B align)

typedef unsigned long long u64;

// Scratch (allocation-free rule: __device__ globals)
__device__ float g_h1[(size_t)LL * CCH];   // 25.7 MB
__device__ float g_P [(size_t)LL * DDIM];  // 231 MB

// ---------- packed f32x2 helpers (FFMA2: PTX-only on sm_103a) ----------
__device__ __forceinline__ u64 dup2f(float a) {
    u64 r; asm("mov.b64 %0, {%1, %1};" : "=l"(r) : "f"(a)); return r;
}
__device__ __forceinline__ void fma2(u64& d, u64 a, u64 b) {
    asm("fma.rn.f32x2 %0, %1, %2, %0;" : "+l"(d) : "l"(a), "l"(b));
}
__device__ __forceinline__ float2 unpk2(u64 v) {
    float2 r; asm("mov.b64 {%0, %1}, %2;" : "=f"(r.x), "=f"(r.y) : "l"(v)); return r;
}

// ---------- implicit unfold gather: t[l, d] ----------
__device__ __forceinline__ float unfold_at(const float* __restrict__ x,
                                           int bimg, int pi, int pj, int d) {
    int c  = d / 9;
    int t9 = d - c * 9;
    int ki = t9 / 3;
    int kj = t9 - ki * 3;
    int ii = pi + ki - 1;
    int jj = pj + kj - 1;
    float v = 0.0f;
    if ((unsigned)ii < HH && (unsigned)jj < WW2)
        v = __ldg(x + ((bimg * CCH + c) * HH + ii) * WW2 + jj);
    return v;
}

// ---------- 8x8 microtile step, packed f32x2 ----------
__device__ __forceinline__ void micro_step(u64 (&acc)[8][4],
                                           const float* __restrict__ Ar,
                                           const float* __restrict__ Br,
                                           int ty, int tx) {
    const float4* ap = (const float4*)(Ar + ty * 8);
    float4 a0 = ap[0], a1 = ap[1];
    const u64* bp = (const u64*)(Br + tx * 8);
    u64 b0 = bp[0], b1 = bp[1], b2 = bp[2], b3 = bp[3];
    float av[8] = {a0.x, a0.y, a0.z, a0.w, a1.x, a1.y, a1.z, a1.w};
#pragma unroll
    for (int i = 0; i < 8; i++) {
        u64 ad = dup2f(av[i]);
        fma2(acc[i][0], ad, b0);
        fma2(acc[i][1], ad, b1);
        fma2(acc[i][2], ad, b2);
        fma2(acc[i][3], ad, b3);
    }
}

// ===================== K1: h1 = relu(unfold(x) @ W1 + b1) =====================
__global__ void __launch_bounds__(256)
k1_conv_relu(const float* __restrict__ x, const float* __restrict__ W1,
             const float* __restrict__ b1) {
    __shared__ float As[2][BK][ROWW];
    __shared__ float Bs[2][BK][ROWW];
    const int tid = threadIdx.x;
    const int tx = tid & 15, ty = tid >> 4;
    const int mbase = blockIdx.y * 128;
    const int nbase = blockIdx.x * 128;

    // A gather assignment: this thread fills As[ak0..ak0+7][am]
    const int am  = tid & 127;
    const int ak0 = (tid >> 7) << 3;
    const int l    = mbase + am;
    const int bimg = l / HWP;
    const int rem  = l - bimg * HWP;
    const int pi   = rem / WW2;
    const int pj   = rem - pi * WW2;

    u64 acc[8][4];
#pragma unroll
    for (int i = 0; i < 8; i++)
#pragma unroll
        for (int j = 0; j < 4; j++) acc[i][j] = 0ull;

    // prologue: chunk 0
#pragma unroll
    for (int q = 0; q < 8; q++)
        As[0][ak0 + q][am] = unfold_at(x, bimg, pi, pj, ak0 + q);
#pragma unroll
    for (int r = 0; r < 2; r++) {
        int v = tid + (r << 8);
        int kk = v >> 5, n4 = (v & 31) << 2;
        *(float4*)&Bs[0][kk][n4] = *(const float4*)(W1 + kk * CCH + nbase + n4);
    }
    __syncthreads();

    const int NK = DDIM / BK;  // 144
    for (int kt = 0; kt < NK; kt++) {
        const int p = kt & 1;
        float ar[8];
        float4 br[2];
        if (kt + 1 < NK) {
            const int kb = (kt + 1) * BK;
#pragma unroll
            for (int q = 0; q < 8; q++)
                ar[q] = unfold_at(x, bimg, pi, pj, kb + ak0 + q);
#pragma unroll
            for (int r = 0; r < 2; r++) {
                int v = tid + (r << 8);
                int kk = v >> 5, n4 = (v & 31) << 2;
                br[r] = *(const float4*)(W1 + (kb + kk) * CCH + nbase + n4);
            }
        }
#pragma unroll
        for (int k = 0; k < BK; k++)
            micro_step(acc, &As[p][k][0], &Bs[p][k][0], ty, tx);
        if (kt + 1 < NK) {
            const int np = p ^ 1;
#pragma unroll
            for (int q = 0; q < 8; q++) As[np][ak0 + q][am] = ar[q];
#pragma unroll
            for (int r = 0; r < 2; r++) {
                int v = tid + (r << 8);
                int kk = v >> 5, n4 = (v & 31) << 2;
                *(float4*)&Bs[np][kk][n4] = br[r];
            }
        }
        __syncthreads();
    }

    // epilogue: +b1, relu, store h1
#pragma unroll
    for (int i = 0; i < 8; i++) {
        int lrow = mbase + (ty << 3) + i;
        float* dst = g_h1 + lrow * CCH + nbase + (tx << 3);
#pragma unroll
        for (int j = 0; j < 4; j++) {
            float2 v = unpk2(acc[i][j]);
            int nc = nbase + (tx << 3) + (j << 1);
            v.x = fmaxf(v.x + __ldg(b1 + nc), 0.0f);
            v.y = fmaxf(v.y + __ldg(b1 + nc + 1), 0.0f);
            *(float2*)(dst + (j << 1)) = v;
        }
    }
}

// ============ K2: P = unfold(x) * sigmoid(h1 @ W2 + b2)  (N = 2304) ============
__global__ void __launch_bounds__(256)
k2_gate(const float* __restrict__ x, const float* __restrict__ W2,
        const float* __restrict__ b2) {
    __shared__ float As[2][BK][ROWW];
    __shared__ float Bs[2][BK][ROWW];
    const int tid = threadIdx.x;
    const int tx = tid & 15, ty = tid >> 4;
    const int mbase = blockIdx.y * 128;
    const int nbase = blockIdx.x * 128;

    u64 acc[8][4];
#pragma unroll
    for (int i = 0; i < 8; i++)
#pragma unroll
        for (int j = 0; j < 4; j++) acc[i][j] = 0ull;

    // prologue chunk 0
#pragma unroll
    for (int r = 0; r < 2; r++) {
        int v = tid + (r << 8);
        int am = v >> 2, kq = (v & 3) << 2;
        float4 a = *(const float4*)(g_h1 + (mbase + am) * CCH + kq);
        As[0][kq + 0][am] = a.x;
        As[0][kq + 1][am] = a.y;
        As[0][kq + 2][am] = a.z;
        As[0][kq + 3][am] = a.w;
        int kk = v >> 5, n4 = (v & 31) << 2;
        *(float4*)&Bs[0][kk][n4] = *(const float4*)(W2 + kk * DDIM + nbase + n4);
    }
    __syncthreads();

    const int NK = CCH / BK;  // 16
    for (int kt = 0; kt < NK; kt++) {
        const int p = kt & 1;
        float4 ar[2], br[2];
        if (kt + 1 < NK) {
            const int kb = (kt + 1) * BK;
#pragma unroll
            for (int r = 0; r < 2; r++) {
                int v = tid + (r << 8);
                int am = v >> 2, kq = (v & 3) << 2;
                ar[r] = *(const float4*)(g_h1 + (mbase + am) * CCH + kb + kq);
                int kk = v >> 5, n4 = (v & 31) << 2;
                br[r] = *(const float4*)(W2 + (kb + kk) * DDIM + nbase + n4);
            }
        }
#pragma unroll
        for (int k = 0; k < BK; k++)
            micro_step(acc, &As[p][k][0], &Bs[p][k][0], ty, tx);
        if (kt + 1 < NK) {
            const int np = p ^ 1;
#pragma unroll
            for (int r = 0; r < 2; r++) {
                int v = tid + (r << 8);
                int am = v >> 2, kq = (v & 3) << 2;
                As[np][kq + 0][am] = ar[r].x;
                As[np][kq + 1][am] = ar[r].y;
                As[np][kq + 2][am] = ar[r].z;
                As[np][kq + 3][am] = ar[r].w;
                int kk = v >> 5, n4 = (v & 31) << 2;
                *(float4*)&Bs[np][kk][n4] = br[r];
            }
        }
        __syncthreads();
    }

    // epilogue: sigmoid gate * gathered t -> g_P
#pragma unroll
    for (int i = 0; i < 8; i++) {
        int lrow = mbase + (ty << 3) + i;
        int bimg = lrow / HWP;
        int rem  = lrow - bimg * HWP;
        int pi   = rem / WW2;
        int pj   = rem - pi * WW2;
        float* dst = g_P + lrow * DDIM + nbase + (tx << 3);
#pragma unroll
        for (int j = 0; j < 4; j++) {
            float2 v = unpk2(acc[i][j]);
            int d0 = nbase + (tx << 3) + (j << 1);
            v.x += __ldg(b2 + d0);
            v.y += __ldg(b2 + d0 + 1);
            float s0 = __fdividef(1.0f, 1.0f + __expf(-v.x));
            float s1 = __fdividef(1.0f, 1.0f + __expf(-v.y));
            float t0 = unfold_at(x, bimg, pi, pj, d0);
            float t1 = unfold_at(x, bimg, pi, pj, d0 + 1);
            float2 o = make_float2(t0 * s0, t1 * s1);
            *(float2*)(dst + (j << 1)) = o;
        }
    }
}

// ===================== K3: out = P @ W3 + b3 =====================
__global__ void __launch_bounds__(256)
k3_proj(const float* __restrict__ W3, const float* __restrict__ b3,
        float* __restrict__ out) {
    __shared__ float As[2][BK][ROWW];
    __shared__ float Bs[2][BK][ROWW];
    const int tid = threadIdx.x;
    const int tx = tid & 15, ty = tid >> 4;
    const int mbase = blockIdx.y * 128;
    const int nbase = blockIdx.x * 128;

    u64 acc[8][4];
#pragma unroll
    for (int i = 0; i < 8; i++)
#pragma unroll
        for (int j = 0; j < 4; j++) acc[i][j] = 0ull;

    // prologue chunk 0
#pragma unroll
    for (int r = 0; r < 2; r++) {
        int v = tid + (r << 8);
        int am = v >> 2, kq = (v & 3) << 2;
        float4 a = *(const float4*)(g_P + (mbase + am) * DDIM + kq);
        As[0][kq + 0][am] = a.x;
        As[0][kq + 1][am] = a.y;
        As[0][kq + 2][am] = a.z;
        As[0][kq + 3][am] = a.w;
        int kk = v >> 5, n4 = (v & 31) << 2;
        *(float4*)&Bs[0][kk][n4] = *(const float4*)(W3 + kk * CCH + nbase + n4);
    }
    __syncthreads();

    const int NK = DDIM / BK;  // 144
    for (int kt = 0; kt < NK; kt++) {
        const int p = kt & 1;
        float4 ar[2], br[2];
        if (kt + 1 < NK) {
            const int kb = (kt + 1) * BK;
#pragma unroll
            for (int r = 0; r < 2; r++) {
                int v = tid + (r << 8);
                int am = v >> 2, kq = (v & 3) << 2;
                ar[r] = *(const float4*)(g_P + (mbase + am) * DDIM + kb + kq);
                int kk = v >> 5, n4 = (v & 31) << 2;
                br[r] = *(const float4*)(W3 + (kb + kk) * CCH + nbase + n4);
            }
        }
#pragma unroll
        for (int k = 0; k < BK; k++)
            micro_step(acc, &As[p][k][0], &Bs[p][k][0], ty, tx);
        if (kt + 1 < NK) {
            const int np = p ^ 1;
#pragma unroll
            for (int r = 0; r < 2; r++) {
                int v = tid + (r << 8);
                int am = v >> 2, kq = (v & 3) << 2;
                As[np][kq + 0][am] = ar[r].x;
                As[np][kq + 1][am] = ar[r].y;
                As[np][kq + 2][am] = ar[r].z;
                As[np][kq + 3][am] = ar[r].w;
                int kk = v >> 5, n4 = (v & 31) << 2;
                *(float4*)&Bs[np][kk][n4] = br[r];
            }
        }
        __syncthreads();
    }

    // epilogue: +b3 -> out
#pragma unroll
    for (int i = 0; i < 8; i++) {
        int lrow = mbase + (ty << 3) + i;
        float* dst = out + lrow * CCH + nbase + (tx << 3);
#pragma unroll
        for (int j = 0; j < 4; j++) {
            float2 v = unpk2(acc[i][j]);
            int nc = nbase + (tx << 3) + (j << 1);
            v.x += __ldg(b3 + nc);
            v.y += __ldg(b3 + nc + 1);
            *(float2*)(dst + (j << 1)) = v;
        }
    }
}

// ===================== launch =====================
extern "C" void kernel_launch(void* const* d_in, const int* in_sizes, int n_in,
                              void* d_out, int out_size) {
    (void)in_sizes; (void)n_in; (void)out_size;
    const float* x  = (const float*)d_in[0];
    const float* W1 = (const float*)d_in[1];
    const float* b1 = (const float*)d_in[2];
    const float* W2 = (const float*)d_in[3];
    const float* b2 = (const float*)d_in[4];
    const float* W3 = (const float*)d_in[5];
    const float* b3 = (const float*)d_in[6];
    float* out = (float*)d_out;

    dim3 blk(256);
    k1_conv_relu<<<dim3(2, 196), blk>>>(x, W1, b1);     // [25088,256]  = t @ W1
    k2_gate     <<<dim3(18, 196), blk>>>(x, W2, b2);    // [25088,2304] = t*sig(h1@W2)
    k3_proj     <<<dim3(2, 196), blk>>>(W3, b3, out);   // [25088,256]  = P @ W3
}

// round 8
// speedup vs baseline: 1.9404x; 1.9404x over previous
#include <cuda_runtime.h>
#include <cuda_bf16.h>

#define HH    56
#define HWP   3136
#define LL    25088
#define CCH   256
#define DDIM  2304

typedef unsigned int u32;
typedef unsigned long long u64;

// ---------------- scratch (__device__ globals; no allocation allowed) ----------------
__device__ __align__(16) __nv_bfloat16 g_t_hi [(size_t)LL * DDIM];
__device__ __align__(16) __nv_bfloat16 g_t_lo [(size_t)LL * DDIM];
__device__ __align__(16) __nv_bfloat16 g_h1_hi[(size_t)LL * CCH];
__device__ __align__(16) __nv_bfloat16 g_h1_lo[(size_t)LL * CCH];
__device__ __align__(16) __nv_bfloat16 g_P_hi [(size_t)LL * DDIM];
__device__ __align__(16) __nv_bfloat16 g_P_lo [(size_t)LL * DDIM];
__device__ __align__(16) __nv_bfloat16 g_w1t_hi[CCH * DDIM], g_w1t_lo[CCH * DDIM];  // [256][2304]
__device__ __align__(16) __nv_bfloat16 g_w2t_hi[DDIM * CCH], g_w2t_lo[DDIM * CCH];  // [2304][256]
__device__ __align__(16) __nv_bfloat16 g_w3t_hi[CCH * DDIM], g_w3t_lo[CCH * DDIM];  // [256][2304]

// ---------------- helpers ----------------
__device__ __forceinline__ u32 smem_u32(const void* p) {
    u32 a;
    asm("{ .reg .u64 t; cvta.to.shared.u64 t, %1; cvt.u32.u64 %0, t; }" : "=r"(a) : "l"(p));
    return a;
}
#define CP_COMMIT() asm volatile("cp.async.commit_group;" ::: "memory")
#define CP_WAIT(n)  asm volatile("cp.async.wait_group %0;" :: "n"(n) : "memory")

__device__ __forceinline__ void ldsm4(u32 (&r)[4], u32 addr) {
    asm volatile("ldmatrix.sync.aligned.m8n8.x4.shared.b16 {%0,%1,%2,%3}, [%4];"
                 : "=r"(r[0]), "=r"(r[1]), "=r"(r[2]), "=r"(r[3]) : "r"(addr));
}
__device__ __forceinline__ void mma16816(float (&c)[4], const u32 (&a)[4], u32 b0, u32 b1) {
    asm volatile(
        "mma.sync.aligned.m16n8k16.row.col.f32.bf16.bf16.f32 "
        "{%0,%1,%2,%3}, {%4,%5,%6,%7}, {%8,%9}, {%0,%1,%2,%3};"
        : "+f"(c[0]), "+f"(c[1]), "+f"(c[2]), "+f"(c[3])
        : "r"(a[0]), "r"(a[1]), "r"(a[2]), "r"(a[3]), "r"(b0), "r"(b1));
}

__device__ __forceinline__ u32 pack2(__nv_bfloat16 a, __nv_bfloat16 b) {
    return (u32)__bfloat16_as_ushort(a) | ((u32)__bfloat16_as_ushort(b) << 16);
}
__device__ __forceinline__ void split2(float v0, float v1, u32& hp, u32& lp) {
    __nv_bfloat16 h0 = __float2bfloat16(v0), h1 = __float2bfloat16(v1);
    __nv_bfloat16 l0 = __float2bfloat16(v0 - __bfloat162float(h0));
    __nv_bfloat16 l1 = __float2bfloat16(v1 - __bfloat162float(h1));
    hp = pack2(h0, h1);
    lp = pack2(l0, l1);
}

// ---------------- smem layout ----------------
// Tiles: 128 rows x 32 bf16, rows padded to 80 bytes (conflict-free ldmatrix).
// comp: 0=AH 1=AL 2=BH 3=BL ; two buffers.
#define TROWB 80
#define TILE_B (128 * TROWB)          // 10240 B
#define TILE_OFF(comp, buf) (((comp) + 4 * (buf)) * TILE_B)
#define SMEM_BYTES (8 * TILE_B)       // 81920 B

// cp.async copy of one 128x32 bf16 tile (row-major src, ld elems)
__device__ __forceinline__ void tile_load(u32 dst, const __nv_bfloat16* __restrict__ src,
                                          int ld, int tid) {
#pragma unroll
    for (int r = 0; r < 2; r++) {
        int i = tid + (r << 8);
        int row = i >> 2, part = i & 3;
        asm volatile("cp.async.cg.shared.global [%0], [%1], 16;"
                     :: "r"(dst + row * TROWB + part * 16),
                        "l"(src + (size_t)row * ld + part * 8) : "memory");
    }
}

__device__ __forceinline__ void load4(u32 sb, int buf, int kb,
                                      const __nv_bfloat16* Ahi, const __nv_bfloat16* Alo, int lda,
                                      const __nv_bfloat16* Bhi, const __nv_bfloat16* Blo, int ldb,
                                      int tid) {
    tile_load(sb + TILE_OFF(0, buf), Ahi + kb, lda, tid);
    tile_load(sb + TILE_OFF(1, buf), Alo + kb, lda, tid);
    tile_load(sb + TILE_OFF(2, buf), Bhi + kb, ldb, tid);
    tile_load(sb + TILE_OFF(3, buf), Blo + kb, ldb, tid);
}

// Mainloop: acc[4][4][4] += (Ahi+Alo)[128xK] @ (Bhi+Blo)[128xK]^T, split-bf16 3-term.
__device__ __forceinline__ void gemm_main(
    u32 sb,
    const __nv_bfloat16* __restrict__ Ahi, const __nv_bfloat16* __restrict__ Alo, int lda,
    const __nv_bfloat16* __restrict__ Bhi, const __nv_bfloat16* __restrict__ Blo, int ldb,
    int NC, float (&acc)[4][4][4]) {
    const int tid = threadIdx.x;
    const int lane = tid & 31, wid = tid >> 5;
    const int wm = wid >> 2, wn = wid & 3;

    // per-lane ldmatrix address components
    const int a_row = wm * 64 + (lane & 15);
    const int a_kb  = (lane >> 4) * 16;                       // bytes
    const int b_row = wn * 32 + (lane & 7) + ((lane >> 4) << 3);
    const int b_kb  = ((lane >> 3) & 1) * 16;                 // bytes

    load4(sb, 0, 0, Ahi, Alo, lda, Bhi, Blo, ldb, tid);
    CP_COMMIT();
    load4(sb, 1, 32, Ahi, Alo, lda, Bhi, Blo, ldb, tid);
    CP_COMMIT();

    for (int it = 0; it < NC; it++) {
        const int buf = it & 1;
        if (it + 1 < NC) { CP_WAIT(1); } else { CP_WAIT(0); }
        __syncthreads();

        const u32 tAH = sb + TILE_OFF(0, buf);
        const u32 tAL = sb + TILE_OFF(1, buf);
        const u32 tBH = sb + TILE_OFF(2, buf);
        const u32 tBL = sb + TILE_OFF(3, buf);
#pragma unroll
        for (int ks = 0; ks < 2; ks++) {
            const int ko = ks * 32;  // bytes within row
            u32 aH[4][4], aL[4][4], bH[2][4], bL[2][4];
#pragma unroll
            for (int mi = 0; mi < 4; mi++)
                ldsm4(aH[mi], tAH + (a_row + mi * 16) * TROWB + ko + a_kb);
#pragma unroll
            for (int ng = 0; ng < 2; ng++)
                ldsm4(bH[ng], tBH + (b_row + ng * 16) * TROWB + ko + b_kb);
#pragma unroll
            for (int mi = 0; mi < 4; mi++)
#pragma unroll
                for (int ni = 0; ni < 4; ni++)
                    mma16816(acc[mi][ni], aH[mi], bH[ni >> 1][(ni & 1) * 2],
                             bH[ni >> 1][(ni & 1) * 2 + 1]);
#pragma unroll
            for (int ng = 0; ng < 2; ng++)
                ldsm4(bL[ng], tBL + (b_row + ng * 16) * TROWB + ko + b_kb);
#pragma unroll
            for (int mi = 0; mi < 4; mi++)
#pragma unroll
                for (int ni = 0; ni < 4; ni++)
                    mma16816(acc[mi][ni], aH[mi], bL[ni >> 1][(ni & 1) * 2],
                             bL[ni >> 1][(ni & 1) * 2 + 1]);
#pragma unroll
            for (int mi = 0; mi < 4; mi++)
                ldsm4(aL[mi], tAL + (a_row + mi * 16) * TROWB + ko + a_kb);
#pragma unroll
            for (int mi = 0; mi < 4; mi++)
#pragma unroll
                for (int ni = 0; ni < 4; ni++)
                    mma16816(acc[mi][ni], aL[mi], bH[ni >> 1][(ni & 1) * 2],
                             bH[ni >> 1][(ni & 1) * 2 + 1]);
        }
        __syncthreads();
        if (it + 2 < NC)
            load4(sb, buf, (it + 2) * 32, Ahi, Alo, lda, Bhi, Blo, ldb, tid);
        CP_COMMIT();
    }
}

// ---------------- pre-kernels ----------------
__global__ void __launch_bounds__(256) unfold_kernel(const float* __restrict__ x) {
    int idx = blockIdx.x * 256 + threadIdx.x;
    int l = idx / 144;
    int d0 = (idx - l * 144) << 4;
    int bimg = l / HWP;
    int rem = l - bimg * HWP;
    int pi = rem / HH;
    int pj = rem - pi * HH;
    u32 hw[8], lw[8];
#pragma unroll
    for (int qq = 0; qq < 8; qq++) {
        float v[2];
#pragma unroll
        for (int s = 0; s < 2; s++) {
            int d = d0 + qq * 2 + s;
            int c = (d * 7282) >> 16;
            int t9 = d - c * 9;
            int ki = t9 / 3;
            int kj = t9 - ki * 3;
            int ii = pi + ki - 1, jj = pj + kj - 1;
            float vv = 0.0f;
            if (((unsigned)ii < 56u) && ((unsigned)jj < 56u))
                vv = __ldg(x + (((size_t)bimg * CCH + c) * HH + ii) * HH + jj);
            v[s] = vv;
        }
        split2(v[0], v[1], hw[qq], lw[qq]);
    }
    size_t o = (size_t)l * DDIM + d0;
    ((uint4*)(g_t_hi + o))[0] = make_uint4(hw[0], hw[1], hw[2], hw[3]);
    ((uint4*)(g_t_hi + o))[1] = make_uint4(hw[4], hw[5], hw[6], hw[7]);
    ((uint4*)(g_t_lo + o))[0] = make_uint4(lw[0], lw[1], lw[2], lw[3]);
    ((uint4*)(g_t_lo + o))[1] = make_uint4(lw[4], lw[5], lw[6], lw[7]);
}

__global__ void __launch_bounds__(256) wsplit_kernel(const float* __restrict__ W1,
                                                     const float* __restrict__ W2,
                                                     const float* __restrict__ W3) {
    int idx = blockIdx.x * 256 + threadIdx.x;
    int m = idx / 589824;
    int r = idx - m * 589824;
    float v;
    __nv_bfloat16 *oh, *ol;
    if (m == 0) {
        int n = r / 2304, k = r - n * 2304;
        v = __ldg(W1 + (size_t)k * 256 + n);
        oh = g_w1t_hi; ol = g_w1t_lo;
    } else if (m == 1) {
        int n = r / 256, k = r - n * 256;
        v = __ldg(W2 + (size_t)k * 2304 + n);
        oh = g_w2t_hi; ol = g_w2t_lo;
    } else {
        int n = r / 2304, k = r - n * 2304;
        v = __ldg(W3 + (size_t)k * 256 + n);
        oh = g_w3t_hi; ol = g_w3t_lo;
    }
    __nv_bfloat16 h = __float2bfloat16(v);
    oh[r] = h;
    ol[r] = __float2bfloat16(v - __bfloat162float(h));
}

// ---------------- GEMM kernels ----------------
__global__ void __launch_bounds__(256, 1) k1_gemm(const float* __restrict__ b1) {
    extern __shared__ char smem[];
    u32 sb = smem_u32(smem);
    const int mbase = blockIdx.y * 128, nbase = blockIdx.x * 128;
    float acc[4][4][4];
#pragma unroll
    for (int i = 0; i < 4; i++)
#pragma unroll
        for (int j = 0; j < 4; j++)
#pragma unroll
            for (int q = 0; q < 4; q++) acc[i][j][q] = 0.0f;
    gemm_main(sb, g_t_hi + (size_t)mbase * DDIM, g_t_lo + (size_t)mbase * DDIM, DDIM,
              g_w1t_hi + (size_t)nbase * DDIM, g_w1t_lo + (size_t)nbase * DDIM, DDIM,
              DDIM / 32, acc);
    const int tid = threadIdx.x, lane = tid & 31, wid = tid >> 5;
    const int wm = wid >> 2, wn = wid & 3;
    u32* stg_hi = (u32*)smem;
    u32* stg_lo = stg_hi + 128 * 65;
#pragma unroll
    for (int mi = 0; mi < 4; mi++)
#pragma unroll
        for (int ni = 0; ni < 4; ni++) {
            int c_loc = wn * 32 + ni * 8 + (lane & 3) * 2;
            int cg = nbase + c_loc;
            float bi0 = __ldg(b1 + cg), bi1 = __ldg(b1 + cg + 1);
            int r0 = wm * 64 + mi * 16 + (lane >> 2);
            u32 hp, lp;
            split2(fmaxf(acc[mi][ni][0] + bi0, 0.0f), fmaxf(acc[mi][ni][1] + bi1, 0.0f), hp, lp);
            stg_hi[r0 * 65 + (c_loc >> 1)] = hp;
            stg_lo[r0 * 65 + (c_loc >> 1)] = lp;
            split2(fmaxf(acc[mi][ni][2] + bi0, 0.0f), fmaxf(acc[mi][ni][3] + bi1, 0.0f), hp, lp);
            stg_hi[(r0 + 8) * 65 + (c_loc >> 1)] = hp;
            stg_lo[(r0 + 8) * 65 + (c_loc >> 1)] = lp;
        }
    __syncthreads();
    for (int i = tid; i < 8192; i += 256) {
        int rr = i >> 6, cp = i & 63;
        size_t o = (size_t)(mbase + rr) * CCH + nbase + cp * 2;
        *(u32*)(g_h1_hi + o) = stg_hi[rr * 65 + cp];
        *(u32*)(g_h1_lo + o) = stg_lo[rr * 65 + cp];
    }
}

__global__ void __launch_bounds__(256, 1) k2_gemm(const float* __restrict__ b2) {
    extern __shared__ char smem[];
    u32 sb = smem_u32(smem);
    const int mbase = blockIdx.y * 128, nbase = blockIdx.x * 128;
    float acc[4][4][4];
#pragma unroll
    for (int i = 0; i < 4; i++)
#pragma unroll
        for (int j = 0; j < 4; j++)
#pragma unroll
            for (int q = 0; q < 4; q++) acc[i][j][q] = 0.0f;
    gemm_main(sb, g_h1_hi + (size_t)mbase * CCH, g_h1_lo + (size_t)mbase * CCH, CCH,
              g_w2t_hi + (size_t)nbase * CCH, g_w2t_lo + (size_t)nbase * CCH, CCH,
              CCH / 32, acc);
    const int tid = threadIdx.x, lane = tid & 31, wid = tid >> 5;
    const int wm = wid >> 2, wn = wid & 3;
    u32* stg_hi = (u32*)smem;
    u32* stg_lo = stg_hi + 128 * 65;
#pragma unroll
    for (int mi = 0; mi < 4; mi++)
#pragma unroll
        for (int ni = 0; ni < 4; ni++) {
            int c_loc = wn * 32 + ni * 8 + (lane & 3) * 2;
            int cg = nbase + c_loc;
            float bi0 = __ldg(b2 + cg), bi1 = __ldg(b2 + cg + 1);
            int r0 = wm * 64 + mi * 16 + (lane >> 2);
#pragma unroll
            for (int h = 0; h < 2; h++) {
                int rr = r0 + h * 8;
                float v0 = acc[mi][ni][h * 2 + 0] + bi0;
                float v1 = acc[mi][ni][h * 2 + 1] + bi1;
                float s0 = __fdividef(1.0f, 1.0f + __expf(-v0));
                float s1 = __fdividef(1.0f, 1.0f + __expf(-v1));
                size_t go = (size_t)(mbase + rr) * DDIM + cg;
                __nv_bfloat162 th = *(const __nv_bfloat162*)(g_t_hi + go);
                __nv_bfloat162 tl = *(const __nv_bfloat162*)(g_t_lo + go);
                float t0 = __bfloat162float(th.x) + __bfloat162float(tl.x);
                float t1 = __bfloat162float(th.y) + __bfloat162float(tl.y);
                u32 hp, lp;
                split2(t0 * s0, t1 * s1, hp, lp);
                stg_hi[rr * 65 + (c_loc >> 1)] = hp;
                stg_lo[rr * 65 + (c_loc >> 1)] = lp;
            }
        }
    __syncthreads();
    for (int i = tid; i < 8192; i += 256) {
        int rr = i >> 6, cp = i & 63;
        size_t o = (size_t)(mbase + rr) * DDIM + nbase + cp * 2;
        *(u32*)(g_P_hi + o) = stg_hi[rr * 65 + cp];
        *(u32*)(g_P_lo + o) = stg_lo[rr * 65 + cp];
    }
}

__global__ void __launch_bounds__(256, 1) k3_gemm(const float* __restrict__ b3,
                                                  float* __restrict__ out) {
    extern __shared__ char smem[];
    u32 sb = smem_u32(smem);
    const int mbase = blockIdx.y * 128, nbase = blockIdx.x * 128;
    float acc[4][4][4];
#pragma unroll
    for (int i = 0; i < 4; i++)
#pragma unroll
        for (int j = 0; j < 4; j++)
#pragma unroll
            for (int q = 0; q < 4; q++) acc[i][j][q] = 0.0f;
    gemm_main(sb, g_P_hi + (size_t)mbase * DDIM, g_P_lo + (size_t)mbase * DDIM, DDIM,
              g_w3t_hi + (size_t)nbase * DDIM, g_w3t_lo + (size_t)nbase * DDIM, DDIM,
              DDIM / 32, acc);
    const int tid = threadIdx.x, lane = tid & 31, wid = tid >> 5;
    const int wm = wid >> 2, wn = wid & 3;
    float* stg = (float*)smem;  // [128][129]
#pragma unroll
    for (int mi = 0; mi < 4; mi++)
#pragma unroll
        for (int ni = 0; ni < 4; ni++) {
            int c_loc = wn * 32 + ni * 8 + (lane & 3) * 2;
            int cg = nbase + c_loc;
            float bi0 = __ldg(b3 + cg), bi1 = __ldg(b3 + cg + 1);
            int r0 = wm * 64 + mi * 16 + (lane >> 2);
            stg[r0 * 129 + c_loc]           = acc[mi][ni][0] + bi0;
            stg[r0 * 129 + c_loc + 1]       = acc[mi][ni][1] + bi1;
            stg[(r0 + 8) * 129 + c_loc]     = acc[mi][ni][2] + bi0;
            stg[(r0 + 8) * 129 + c_loc + 1] = acc[mi][ni][3] + bi1;
        }
    __syncthreads();
    for (int i = tid; i < 16384; i += 256) {
        int rr = i >> 7, c = i & 127;
        out[(size_t)(mbase + rr) * CCH + nbase + c] = stg[rr * 129 + c];
    }
}

// ---------------- launch ----------------
extern "C" void kernel_launch(void* const* d_in, const int* in_sizes, int n_in,
                              void* d_out, int out_size) {
    (void)in_sizes; (void)n_in; (void)out_size;
    const float* x  = (const float*)d_in[0];
    const float* W1 = (const float*)d_in[1];
    const float* b1 = (const float*)d_in[2];
    const float* W2 = (const float*)d_in[3];
    const float* b2 = (const float*)d_in[4];
    const float* W3 = (const float*)d_in[5];
    const float* b3 = (const float*)d_in[6];
    float* out = (float*)d_out;

    cudaFuncSetAttribute(k1_gemm, cudaFuncAttributeMaxDynamicSharedMemorySize, SMEM_BYTES);
    cudaFuncSetAttribute(k2_gemm, cudaFuncAttributeMaxDynamicSharedMemorySize, SMEM_BYTES);
    cudaFuncSetAttribute(k3_gemm, cudaFuncAttributeMaxDynamicSharedMemorySize, SMEM_BYTES);

    wsplit_kernel<<<6912, 256>>>(W1, W2, W3);             // 3 * 589824 weight elems
    unfold_kernel<<<14112, 256>>>(x);                     // 25088 * 144 items
    k1_gemm<<<dim3(2, 196), 256, SMEM_BYTES>>>(b1);       // h1 = relu(t@W1+b1)  (split bf16)
    k2_gemm<<<dim3(18, 196), 256, SMEM_BYTES>>>(b2);      // P  = t * sigmoid(h1@W2+b2)
    k3_gemm<<<dim3(2, 196), 256, SMEM_BYTES>>>(b3, out);  // out = P@W3 + b3
}